// round 6
// baseline (speedup 1.0000x reference)
#include <cuda_runtime.h>

#define DIMC 1024
#define NH   16
#define HD   64
#define BATCH 2
#define SEQ  2048
#define MTOT (BATCH*SEQ)   // 4096

// Scratch (no cudaMalloc allowed): Q/K/V in [B*H][T][HD] layout, attention out in [B*T][C]
__device__ float g_q[BATCH*NH*SEQ*HD];
__device__ float g_k[BATCH*NH*SEQ*HD];
__device__ float g_v[BATCH*NH*SEQ*HD];
__device__ float g_att[MTOT*DIMC];

// ---------------------------------------------------------------------------
// Kernel 1: QKV GEMM  C[4096,3072] = x[4096,1024] @ W_qkv[1024,3072] + b_qkv
// Epilogue scatters into g_q / g_k / g_v with [B*H][T][HD] layout.
// 128x128 block tile, BK=8, 8x8 per-thread micro-tile, 256 threads.
// ---------------------------------------------------------------------------
__global__ void __launch_bounds__(256) qkv_gemm_kernel(
    const float* __restrict__ A, const float* __restrict__ W,
    const float* __restrict__ bias)
{
    __shared__ float As[8][128];
    __shared__ float Bs[8][128];

    const int tid = threadIdx.x;
    const int tx = tid & 15;        // 0..15
    const int ty = tid >> 4;        // 0..15
    const int bm = blockIdx.y;      // 0..31
    const int bn = blockIdx.x;      // 0..23

    const int a_row = tid >> 1;           // 0..127
    const int a_col = (tid & 1) * 4;      // 0 or 4
    const int b_row = tid >> 5;           // 0..7
    const int b_col = (tid & 31) * 4;     // 0..124

    const float* Ab = A + (size_t)(bm * 128) * 1024;
    const float* Wb = W + bn * 128;

    float acc[8][8];
#pragma unroll
    for (int i = 0; i < 8; ++i)
#pragma unroll
        for (int j = 0; j < 8; ++j) acc[i][j] = 0.0f;

    for (int k0 = 0; k0 < 1024; k0 += 8) {
        float4 av = *(const float4*)(Ab + a_row * 1024 + k0 + a_col);
        As[a_col + 0][a_row] = av.x;
        As[a_col + 1][a_row] = av.y;
        As[a_col + 2][a_row] = av.z;
        As[a_col + 3][a_row] = av.w;
        float4 bv = *(const float4*)(Wb + (size_t)(k0 + b_row) * 3072 + b_col);
        *(float4*)&Bs[b_row][b_col] = bv;
        __syncthreads();

#pragma unroll
        for (int k = 0; k < 8; ++k) {
            float4 a0 = *(const float4*)&As[k][ty * 8];
            float4 a1 = *(const float4*)&As[k][ty * 8 + 4];
            float4 b0 = *(const float4*)&Bs[k][tx * 8];
            float4 b1 = *(const float4*)&Bs[k][tx * 8 + 4];
            float af[8] = {a0.x, a0.y, a0.z, a0.w, a1.x, a1.y, a1.z, a1.w};
            float bf[8] = {b0.x, b0.y, b0.z, b0.w, b1.x, b1.y, b1.z, b1.w};
#pragma unroll
            for (int i = 0; i < 8; ++i)
#pragma unroll
                for (int j = 0; j < 8; ++j)
                    acc[i][j] = fmaf(af[i], bf[j], acc[i][j]);
        }
        __syncthreads();
    }

    // Epilogue: add bias, scatter to q/k/v head layout
    const int m0 = bm * 128 + ty * 8;
    const int n0 = bn * 128 + tx * 8;
#pragma unroll
    for (int i = 0; i < 8; ++i) {
        const int m = m0 + i;
        const int b = m >> 11;          // /2048
        const int t = m & 2047;
#pragma unroll
        for (int j = 0; j < 8; ++j) {
            const int n = n0 + j;
            const float val = acc[i][j] + bias[n];
            const int sec = n >> 10;    // 0=q 1=k 2=v
            const int c = n & 1023;
            const int h = c >> 6;
            const int d = c & 63;
            float* dst = (sec == 0) ? g_q : (sec == 1) ? g_k : g_v;
            dst[((size_t)(b * NH + h) * SEQ + t) * HD + d] = val;
        }
    }
}

// ---------------------------------------------------------------------------
// Kernel 2: flash attention (fp32, online softmax).
// Grid: (q_tile=16, bh=32). Block 256 threads handles 128 query rows x 64 dim.
// KV processed in 32 tiles of 64 keys.
// Dynamic smem: Qs[64][132] (d-major), Ks[64][68] (d-major), Vs[64][64],
//               Ps[64][129] (k-major).
// ---------------------------------------------------------------------------
#define QS_STRIDE 132
#define KS_STRIDE 68
#define PS_STRIDE 129
#define ATTN_SMEM_FLOATS (64*QS_STRIDE + 64*KS_STRIDE + 64*64 + 64*PS_STRIDE)
#define ATTN_SMEM_BYTES  (ATTN_SMEM_FLOATS * 4)

__global__ void __launch_bounds__(256) attn_kernel()
{
    extern __shared__ float smem[];
    float* Qs = smem;                      // [d][r]   64 x 132
    float* Ks = Qs + 64 * QS_STRIDE;       // [d][c]   64 x 68
    float* Vs = Ks + 64 * KS_STRIDE;       // [k][d]   64 x 64
    float* Ps = Vs + 64 * 64;              // [k][r]   64 x 129

    const int tid = threadIdx.x;
    const int tx = tid & 15;   // 4 cols each
    const int ty = tid >> 4;   // 8 rows each
    const int bh = blockIdx.y;             // 0..31
    const int q0 = blockIdx.x * 128;

    const float scale = 0.125f;            // 1/sqrt(64)

    // Load Q tile (scaled), transposed to d-major
    const float* qptr = g_q + ((size_t)bh * SEQ + q0) * HD;
#pragma unroll
    for (int l = 0; l < 8; ++l) {
        int lin = tid + l * 256;           // 0..2047
        int r = lin >> 4;                  // 0..127
        int d = (lin & 15) * 4;
        float4 v = *(const float4*)(qptr + r * HD + d);
        Qs[(d + 0) * QS_STRIDE + r] = v.x * scale;
        Qs[(d + 1) * QS_STRIDE + r] = v.y * scale;
        Qs[(d + 2) * QS_STRIDE + r] = v.z * scale;
        Qs[(d + 3) * QS_STRIDE + r] = v.w * scale;
    }

    float o[8][4];
    float mi[8], li[8];
#pragma unroll
    for (int i = 0; i < 8; ++i) {
        mi[i] = -1e30f;
        li[i] = 0.0f;
#pragma unroll
        for (int j = 0; j < 4; ++j) o[i][j] = 0.0f;
    }

    for (int kt = 0; kt < 32; ++kt) {
        const int kb = kt * 64;
        const float* kptr = g_k + ((size_t)bh * SEQ + kb) * HD;
        const float* vptr = g_v + ((size_t)bh * SEQ + kb) * HD;
        __syncthreads();   // guard smem reuse from previous iteration
#pragma unroll
        for (int l = 0; l < 4; ++l) {
            int lin = tid + l * 256;       // 0..1023
            int r = lin >> 4;              // 0..63
            int d = (lin & 15) * 4;
            float4 kv = *(const float4*)(kptr + r * HD + d);
            Ks[(d + 0) * KS_STRIDE + r] = kv.x;
            Ks[(d + 1) * KS_STRIDE + r] = kv.y;
            Ks[(d + 2) * KS_STRIDE + r] = kv.z;
            Ks[(d + 3) * KS_STRIDE + r] = kv.w;
            float4 vv = *(const float4*)(vptr + r * HD + d);
            *(float4*)&Vs[r * 64 + d] = vv;
        }
        __syncthreads();

        // S = Q @ K^T  (128 x 64 tile; thread owns 8x4)
        float s[8][4];
#pragma unroll
        for (int i = 0; i < 8; ++i)
#pragma unroll
            for (int j = 0; j < 4; ++j) s[i][j] = 0.0f;

#pragma unroll 4
        for (int d = 0; d < 64; ++d) {
            float4 a0 = *(const float4*)&Qs[d * QS_STRIDE + ty * 8];
            float4 a1 = *(const float4*)&Qs[d * QS_STRIDE + ty * 8 + 4];
            float4 kb4 = *(const float4*)&Ks[d * KS_STRIDE + tx * 4];
            float af[8] = {a0.x, a0.y, a0.z, a0.w, a1.x, a1.y, a1.z, a1.w};
            float bf[4] = {kb4.x, kb4.y, kb4.z, kb4.w};
#pragma unroll
            for (int i = 0; i < 8; ++i)
#pragma unroll
                for (int j = 0; j < 4; ++j)
                    s[i][j] = fmaf(af[i], bf[j], s[i][j]);
        }

        // Online softmax per row (row spread across 16 lanes of a half-warp)
#pragma unroll
        for (int i = 0; i < 8; ++i) {
            float mloc = fmaxf(fmaxf(s[i][0], s[i][1]), fmaxf(s[i][2], s[i][3]));
            mloc = fmaxf(mloc, __shfl_xor_sync(0xffffffffu, mloc, 8));
            mloc = fmaxf(mloc, __shfl_xor_sync(0xffffffffu, mloc, 4));
            mloc = fmaxf(mloc, __shfl_xor_sync(0xffffffffu, mloc, 2));
            mloc = fmaxf(mloc, __shfl_xor_sync(0xffffffffu, mloc, 1));
            float mnew = fmaxf(mi[i], mloc);
            float p0 = __expf(s[i][0] - mnew);
            float p1 = __expf(s[i][1] - mnew);
            float p2 = __expf(s[i][2] - mnew);
            float p3 = __expf(s[i][3] - mnew);
            float lsum = (p0 + p1) + (p2 + p3);
            lsum += __shfl_xor_sync(0xffffffffu, lsum, 8);
            lsum += __shfl_xor_sync(0xffffffffu, lsum, 4);
            lsum += __shfl_xor_sync(0xffffffffu, lsum, 2);
            lsum += __shfl_xor_sync(0xffffffffu, lsum, 1);
            float corr = __expf(mi[i] - mnew);
            li[i] = li[i] * corr + lsum;
            mi[i] = mnew;
            o[i][0] *= corr; o[i][1] *= corr; o[i][2] *= corr; o[i][3] *= corr;
            const int r = ty * 8 + i;
            Ps[(tx * 4 + 0) * PS_STRIDE + r] = p0;
            Ps[(tx * 4 + 1) * PS_STRIDE + r] = p1;
            Ps[(tx * 4 + 2) * PS_STRIDE + r] = p2;
            Ps[(tx * 4 + 3) * PS_STRIDE + r] = p3;
        }
        __syncthreads();

        // O += P @ V  (thread owns 8 rows x 4 dims)
#pragma unroll 4
        for (int kk = 0; kk < 64; ++kk) {
            float pa[8];
#pragma unroll
            for (int i = 0; i < 8; ++i) pa[i] = Ps[kk * PS_STRIDE + ty * 8 + i];
            float4 vb = *(const float4*)&Vs[kk * 64 + tx * 4];
#pragma unroll
            for (int i = 0; i < 8; ++i) {
                o[i][0] = fmaf(pa[i], vb.x, o[i][0]);
                o[i][1] = fmaf(pa[i], vb.y, o[i][1]);
                o[i][2] = fmaf(pa[i], vb.z, o[i][2]);
                o[i][3] = fmaf(pa[i], vb.w, o[i][3]);
            }
        }
    }

    // Epilogue: normalize, write to g_att in [B*T][C] layout
    const int b = bh >> 4;
    const int h = bh & 15;
#pragma unroll
    for (int i = 0; i < 8; ++i) {
        const int t = q0 + ty * 8 + i;
        const float inv = 1.0f / li[i];
        float4 ov;
        ov.x = o[i][0] * inv; ov.y = o[i][1] * inv;
        ov.z = o[i][2] * inv; ov.w = o[i][3] * inv;
        *(float4*)&g_att[((size_t)(b * SEQ) + t) * DIMC + h * HD + tx * 4] = ov;
    }
}

// ---------------------------------------------------------------------------
// Kernel 3: Proj GEMM  out[4096,1024] = g_att @ W_proj[1024,1024] + b_proj
// ---------------------------------------------------------------------------
__global__ void __launch_bounds__(256) proj_gemm_kernel(
    const float* __restrict__ W, const float* __restrict__ bias,
    float* __restrict__ out)
{
    __shared__ float As[8][128];
    __shared__ float Bs[8][128];

    const int tid = threadIdx.x;
    const int tx = tid & 15;
    const int ty = tid >> 4;
    const int bm = blockIdx.y;   // 0..31
    const int bn = blockIdx.x;   // 0..7

    const int a_row = tid >> 1;
    const int a_col = (tid & 1) * 4;
    const int b_row = tid >> 5;
    const int b_col = (tid & 31) * 4;

    const float* Ab = g_att + (size_t)(bm * 128) * 1024;
    const float* Wb = W + bn * 128;

    float acc[8][8];
#pragma unroll
    for (int i = 0; i < 8; ++i)
#pragma unroll
        for (int j = 0; j < 8; ++j) acc[i][j] = 0.0f;

    for (int k0 = 0; k0 < 1024; k0 += 8) {
        float4 av = *(const float4*)(Ab + a_row * 1024 + k0 + a_col);
        As[a_col + 0][a_row] = av.x;
        As[a_col + 1][a_row] = av.y;
        As[a_col + 2][a_row] = av.z;
        As[a_col + 3][a_row] = av.w;
        float4 bv = *(const float4*)(Wb + (size_t)(k0 + b_row) * 1024 + b_col);
        *(float4*)&Bs[b_row][b_col] = bv;
        __syncthreads();

#pragma unroll
        for (int k = 0; k < 8; ++k) {
            float4 a0 = *(const float4*)&As[k][ty * 8];
            float4 a1 = *(const float4*)&As[k][ty * 8 + 4];
            float4 b0 = *(const float4*)&Bs[k][tx * 8];
            float4 b1 = *(const float4*)&Bs[k][tx * 8 + 4];
            float af[8] = {a0.x, a0.y, a0.z, a0.w, a1.x, a1.y, a1.z, a1.w};
            float bf[8] = {b0.x, b0.y, b0.z, b0.w, b1.x, b1.y, b1.z, b1.w};
#pragma unroll
            for (int i = 0; i < 8; ++i)
#pragma unroll
                for (int j = 0; j < 8; ++j)
                    acc[i][j] = fmaf(af[i], bf[j], acc[i][j]);
        }
        __syncthreads();
    }

    const int m0 = bm * 128 + ty * 8;
    const int n0 = bn * 128 + tx * 8;
#pragma unroll
    for (int i = 0; i < 8; ++i) {
#pragma unroll
        for (int j = 0; j < 8; j += 4) {
            float4 ov;
            ov.x = acc[i][j + 0] + bias[n0 + j + 0];
            ov.y = acc[i][j + 1] + bias[n0 + j + 1];
            ov.z = acc[i][j + 2] + bias[n0 + j + 2];
            ov.w = acc[i][j + 3] + bias[n0 + j + 3];
            *(float4*)&out[(size_t)(m0 + i) * 1024 + n0 + j] = ov;
        }
    }
}

// ---------------------------------------------------------------------------
extern "C" void kernel_launch(void* const* d_in, const int* in_sizes, int n_in,
                              void* d_out, int out_size)
{
    const float* x      = (const float*)d_in[0];
    const float* W_qkv  = (const float*)d_in[1];
    const float* b_qkv  = (const float*)d_in[2];
    const float* W_proj = (const float*)d_in[3];
    const float* b_proj = (const float*)d_in[4];
    float* out = (float*)d_out;

    cudaFuncSetAttribute(attn_kernel,
                         cudaFuncAttributeMaxDynamicSharedMemorySize,
                         ATTN_SMEM_BYTES);

    qkv_gemm_kernel<<<dim3(24, 32), 256>>>(x, W_qkv, b_qkv);
    attn_kernel<<<dim3(16, 32), 256, ATTN_SMEM_BYTES>>>();
    proj_gemm_kernel<<<dim3(8, 32), 256>>>(W_proj, b_proj, out);
}

// round 16
// speedup vs baseline: 2.0277x; 2.0277x over previous
#include <cuda_runtime.h>
#include <cstdint>

#define DIMC 1024
#define NH   16
#define HD   64
#define BATCH 2
#define SEQ  2048
#define MTOT (BATCH*SEQ)   // 4096

// Scratch: Q/K/V in [B*H][T][HD] layout, attention out in [B*T][C]
__device__ float g_q[BATCH*NH*SEQ*HD];
__device__ float g_k[BATCH*NH*SEQ*HD];
__device__ float g_v[BATCH*NH*SEQ*HD];
__device__ float g_att[MTOT*DIMC];

// ===========================================================================
// tf32 helpers (base PTX — compiles for plain sm_103 target)
// ===========================================================================
__device__ __forceinline__ uint32_t to_tf32_bits(float v) {
    uint32_t r;
    asm("cvt.rna.tf32.f32 %0, %1;" : "=r"(r) : "f"(v));
    return r;
}

__device__ __forceinline__ void mma_tf32(float* c,
                                         uint32_t a0, uint32_t a1,
                                         uint32_t a2, uint32_t a3,
                                         uint32_t b0, uint32_t b1) {
    asm volatile(
        "mma.sync.aligned.m16n8k8.row.col.f32.tf32.tf32.f32 "
        "{%0,%1,%2,%3}, {%4,%5,%6,%7}, {%8,%9}, {%0,%1,%2,%3};"
        : "+f"(c[0]), "+f"(c[1]), "+f"(c[2]), "+f"(c[3])
        : "r"(a0), "r"(a1), "r"(a2), "r"(a3), "r"(b0), "r"(b1));
}

// ===========================================================================
// mma.sync tf32x3 GEMM:  C[128m x 128n tile] = A[m,1024] @ W[1024,N] (+bias)
// MODE 0: A = x, W = W_qkv (LDW 3072), epilogue scatters to g_q/g_k/g_v
// MODE 1: A = g_att, W = W_proj (LDW 1024), epilogue writes to out
// 256 threads = 8 warps (2m x 4n), warp tile 64x32, BK=32.
// SMEM: As big/small [128][stride 36], Bs big/small [32][stride 136].
// ===========================================================================
#define AS_STRIDE 36
#define BS_STRIDE 136
#define AS_FLOATS (128 * AS_STRIDE)      // 4608
#define BS_FLOATS (32 * BS_STRIDE)       // 4352
#define GEMM_SMEM_FLOATS (2 * AS_FLOATS + 2 * BS_FLOATS)   // 17920
#define GEMM_SMEM_BYTES  (GEMM_SMEM_FLOATS * 4)            // 71680

template <int MODE>
__global__ void __launch_bounds__(256) gemm_mma_kernel(
    const float* __restrict__ A, const float* __restrict__ W,
    const float* __restrict__ bias, float* __restrict__ out)
{
    constexpr int LDW = (MODE == 0) ? 3072 : 1024;
    extern __shared__ float smem[];
    float* AsB = smem;
    float* AsS = AsB + AS_FLOATS;
    float* BsB = AsS + AS_FLOATS;
    float* BsS = BsB + BS_FLOATS;

    const int tid = threadIdx.x;
    const int wid = tid >> 5;
    const int lane = tid & 31;
    const int g   = lane >> 2;    // 0..7
    const int tig = lane & 3;     // 0..3
    const int warp_m = wid >> 2;  // 0..1
    const int warp_n = wid & 3;   // 0..3
    const int bn = blockIdx.x;
    const int bm = blockIdx.y;

    const float* Aptr = (MODE == 1) ? (const float*)g_att : A;
    const float* Ab = Aptr + (size_t)(bm * 128) * 1024;
    const float* Wb = W + bn * 128;

    float acc[4][4][4];
#pragma unroll
    for (int mt = 0; mt < 4; ++mt)
#pragma unroll
        for (int nt = 0; nt < 4; ++nt)
#pragma unroll
            for (int q = 0; q < 4; ++q) acc[mt][nt][q] = 0.0f;

    for (int s = 0; s < 32; ++s) {
        const int k0 = s * 32;

        // ---- hoisted global loads (overlap with previous stage's MMAs) ----
        float4 av[4], wv[4];
#pragma unroll
        for (int j = 0; j < 4; ++j) {
            int idx = tid + j * 256;            // 0..1023
            int row = idx >> 3;                 // 0..127
            int kq  = (idx & 7) * 4;            // 0..28
            av[j] = *(const float4*)(Ab + (size_t)row * 1024 + k0 + kq);
        }
#pragma unroll
        for (int j = 0; j < 4; ++j) {
            int idx = tid + j * 256;            // 0..1023
            int r = idx >> 5;                   // 0..31
            int c = (idx & 31) * 4;             // 0..124
            wv[j] = *(const float4*)(Wb + (size_t)(k0 + r) * LDW + c);
        }

        __syncthreads();   // previous stage fully consumed

        // ---- split + store to SMEM ----
#pragma unroll
        for (int j = 0; j < 4; ++j) {
            int idx = tid + j * 256;
            int row = idx >> 3;
            int kq  = (idx & 7) * 4;
            float4 hb, hs;
            hb.x = __uint_as_float(to_tf32_bits(av[j].x)); hs.x = __uint_as_float(to_tf32_bits(av[j].x - hb.x));
            hb.y = __uint_as_float(to_tf32_bits(av[j].y)); hs.y = __uint_as_float(to_tf32_bits(av[j].y - hb.y));
            hb.z = __uint_as_float(to_tf32_bits(av[j].z)); hs.z = __uint_as_float(to_tf32_bits(av[j].z - hb.z));
            hb.w = __uint_as_float(to_tf32_bits(av[j].w)); hs.w = __uint_as_float(to_tf32_bits(av[j].w - hb.w));
            *(float4*)&AsB[row * AS_STRIDE + kq] = hb;
            *(float4*)&AsS[row * AS_STRIDE + kq] = hs;
        }
#pragma unroll
        for (int j = 0; j < 4; ++j) {
            int idx = tid + j * 256;
            int r = idx >> 5;
            int c = (idx & 31) * 4;
            float4 hb, hs;
            hb.x = __uint_as_float(to_tf32_bits(wv[j].x)); hs.x = __uint_as_float(to_tf32_bits(wv[j].x - hb.x));
            hb.y = __uint_as_float(to_tf32_bits(wv[j].y)); hs.y = __uint_as_float(to_tf32_bits(wv[j].y - hb.y));
            hb.z = __uint_as_float(to_tf32_bits(wv[j].z)); hs.z = __uint_as_float(to_tf32_bits(wv[j].z - hb.z));
            hb.w = __uint_as_float(to_tf32_bits(wv[j].w)); hs.w = __uint_as_float(to_tf32_bits(wv[j].w - hb.w));
            *(float4*)&BsB[r * BS_STRIDE + c] = hb;
            *(float4*)&BsS[r * BS_STRIDE + c] = hs;
        }
        __syncthreads();

        // ---- 4 k-steps of m16n8k8 ----
#pragma unroll
        for (int ks = 0; ks < 4; ++ks) {
            const int kk = ks * 8;
            uint32_t ab[4][4], asm_[4][4];
#pragma unroll
            for (int mt = 0; mt < 4; ++mt) {
                const int m = warp_m * 64 + mt * 16;
                const int r0 = (m + g) * AS_STRIDE + kk + tig;
                const int r1 = (m + g + 8) * AS_STRIDE + kk + tig;
                ab[mt][0] = __float_as_uint(AsB[r0]);
                ab[mt][1] = __float_as_uint(AsB[r1]);
                ab[mt][2] = __float_as_uint(AsB[r0 + 4]);
                ab[mt][3] = __float_as_uint(AsB[r1 + 4]);
                asm_[mt][0] = __float_as_uint(AsS[r0]);
                asm_[mt][1] = __float_as_uint(AsS[r1]);
                asm_[mt][2] = __float_as_uint(AsS[r0 + 4]);
                asm_[mt][3] = __float_as_uint(AsS[r1 + 4]);
            }
            uint32_t bb[4][2], bs[4][2];
#pragma unroll
            for (int nt = 0; nt < 4; ++nt) {
                const int n = warp_n * 32 + nt * 8 + g;
                bb[nt][0] = __float_as_uint(BsB[(kk + tig) * BS_STRIDE + n]);
                bb[nt][1] = __float_as_uint(BsB[(kk + tig + 4) * BS_STRIDE + n]);
                bs[nt][0] = __float_as_uint(BsS[(kk + tig) * BS_STRIDE + n]);
                bs[nt][1] = __float_as_uint(BsS[(kk + tig + 4) * BS_STRIDE + n]);
            }
#pragma unroll
            for (int mt = 0; mt < 4; ++mt)
#pragma unroll
                for (int nt = 0; nt < 4; ++nt) {
                    mma_tf32(acc[mt][nt], ab[mt][0], ab[mt][1], ab[mt][2], ab[mt][3],
                             bb[nt][0], bb[nt][1]);
                    mma_tf32(acc[mt][nt], ab[mt][0], ab[mt][1], ab[mt][2], ab[mt][3],
                             bs[nt][0], bs[nt][1]);
                    mma_tf32(acc[mt][nt], asm_[mt][0], asm_[mt][1], asm_[mt][2], asm_[mt][3],
                             bb[nt][0], bb[nt][1]);
                }
        }
    }

    // ---- epilogue ----
#pragma unroll
    for (int mt = 0; mt < 4; ++mt) {
        const int mrow0 = bm * 128 + warp_m * 64 + mt * 16 + g;
#pragma unroll
        for (int nt = 0; nt < 4; ++nt) {
            const int ncol0 = bn * 128 + warp_n * 32 + nt * 8 + tig * 2;
#pragma unroll
            for (int q = 0; q < 4; ++q) {
                const int m = mrow0 + ((q >> 1) ? 8 : 0);
                const int n = ncol0 + (q & 1);
                const float val = acc[mt][nt][q] + bias[n];
                if (MODE == 0) {
                    const int b = m >> 11;
                    const int t = m & 2047;
                    const int sec = n >> 10;
                    const int c = n & 1023;
                    const int h = c >> 6;
                    const int d = c & 63;
                    float* dst = (sec == 0) ? g_q : (sec == 1) ? g_k : g_v;
                    dst[((size_t)(b * NH + h) * SEQ + t) * HD + d] = val;
                } else {
                    out[(size_t)m * 1024 + n] = val;
                }
            }
        }
    }
}

// ---------------------------------------------------------------------------
// Kernel 2: flash attention (fp32, online softmax) — unchanged (passing, R5).
// ---------------------------------------------------------------------------
#define QS_STRIDE 132
#define KS_STRIDE 68
#define PS_STRIDE 129
#define ATTN_SMEM_FLOATS (64*QS_STRIDE + 64*KS_STRIDE + 64*64 + 64*PS_STRIDE)
#define ATTN_SMEM_BYTES  (ATTN_SMEM_FLOATS * 4)

__global__ void __launch_bounds__(256) attn_kernel()
{
    extern __shared__ float smem[];
    float* Qs = smem;
    float* Ks = Qs + 64 * QS_STRIDE;
    float* Vs = Ks + 64 * KS_STRIDE;
    float* Ps = Vs + 64 * 64;

    const int tid = threadIdx.x;
    const int tx = tid & 15;
    const int ty = tid >> 4;
    const int bh = blockIdx.y;
    const int q0 = blockIdx.x * 128;

    const float scale = 0.125f;

    const float* qptr = g_q + ((size_t)bh * SEQ + q0) * HD;
#pragma unroll
    for (int l = 0; l < 8; ++l) {
        int lin = tid + l * 256;
        int r = lin >> 4;
        int d = (lin & 15) * 4;
        float4 v = *(const float4*)(qptr + r * HD + d);
        Qs[(d + 0) * QS_STRIDE + r] = v.x * scale;
        Qs[(d + 1) * QS_STRIDE + r] = v.y * scale;
        Qs[(d + 2) * QS_STRIDE + r] = v.z * scale;
        Qs[(d + 3) * QS_STRIDE + r] = v.w * scale;
    }

    float o[8][4];
    float mi[8], li[8];
#pragma unroll
    for (int i = 0; i < 8; ++i) {
        mi[i] = -1e30f;
        li[i] = 0.0f;
#pragma unroll
        for (int j = 0; j < 4; ++j) o[i][j] = 0.0f;
    }

    for (int kt = 0; kt < 32; ++kt) {
        const int kb = kt * 64;
        const float* kptr = g_k + ((size_t)bh * SEQ + kb) * HD;
        const float* vptr = g_v + ((size_t)bh * SEQ + kb) * HD;
        __syncthreads();
#pragma unroll
        for (int l = 0; l < 4; ++l) {
            int lin = tid + l * 256;
            int r = lin >> 4;
            int d = (lin & 15) * 4;
            float4 kv = *(const float4*)(kptr + r * HD + d);
            Ks[(d + 0) * KS_STRIDE + r] = kv.x;
            Ks[(d + 1) * KS_STRIDE + r] = kv.y;
            Ks[(d + 2) * KS_STRIDE + r] = kv.z;
            Ks[(d + 3) * KS_STRIDE + r] = kv.w;
            float4 vv = *(const float4*)(vptr + r * HD + d);
            *(float4*)&Vs[r * 64 + d] = vv;
        }
        __syncthreads();

        float s[8][4];
#pragma unroll
        for (int i = 0; i < 8; ++i)
#pragma unroll
            for (int j = 0; j < 4; ++j) s[i][j] = 0.0f;

#pragma unroll 4
        for (int d = 0; d < 64; ++d) {
            float4 a0 = *(const float4*)&Qs[d * QS_STRIDE + ty * 8];
            float4 a1 = *(const float4*)&Qs[d * QS_STRIDE + ty * 8 + 4];
            float4 kb4 = *(const float4*)&Ks[d * KS_STRIDE + tx * 4];
            float af[8] = {a0.x, a0.y, a0.z, a0.w, a1.x, a1.y, a1.z, a1.w};
            float bf[4] = {kb4.x, kb4.y, kb4.z, kb4.w};
#pragma unroll
            for (int i = 0; i < 8; ++i)
#pragma unroll
                for (int j = 0; j < 4; ++j)
                    s[i][j] = fmaf(af[i], bf[j], s[i][j]);
        }

#pragma unroll
        for (int i = 0; i < 8; ++i) {
            float mloc = fmaxf(fmaxf(s[i][0], s[i][1]), fmaxf(s[i][2], s[i][3]));
            mloc = fmaxf(mloc, __shfl_xor_sync(0xffffffffu, mloc, 8));
            mloc = fmaxf(mloc, __shfl_xor_sync(0xffffffffu, mloc, 4));
            mloc = fmaxf(mloc, __shfl_xor_sync(0xffffffffu, mloc, 2));
            mloc = fmaxf(mloc, __shfl_xor_sync(0xffffffffu, mloc, 1));
            float mnew = fmaxf(mi[i], mloc);
            float p0 = __expf(s[i][0] - mnew);
            float p1 = __expf(s[i][1] - mnew);
            float p2 = __expf(s[i][2] - mnew);
            float p3 = __expf(s[i][3] - mnew);
            float lsum = (p0 + p1) + (p2 + p3);
            lsum += __shfl_xor_sync(0xffffffffu, lsum, 8);
            lsum += __shfl_xor_sync(0xffffffffu, lsum, 4);
            lsum += __shfl_xor_sync(0xffffffffu, lsum, 2);
            lsum += __shfl_xor_sync(0xffffffffu, lsum, 1);
            float corr = __expf(mi[i] - mnew);
            li[i] = li[i] * corr + lsum;
            mi[i] = mnew;
            o[i][0] *= corr; o[i][1] *= corr; o[i][2] *= corr; o[i][3] *= corr;
            const int r = ty * 8 + i;
            Ps[(tx * 4 + 0) * PS_STRIDE + r] = p0;
            Ps[(tx * 4 + 1) * PS_STRIDE + r] = p1;
            Ps[(tx * 4 + 2) * PS_STRIDE + r] = p2;
            Ps[(tx * 4 + 3) * PS_STRIDE + r] = p3;
        }
        __syncthreads();

#pragma unroll 4
        for (int kk = 0; kk < 64; ++kk) {
            float pa[8];
#pragma unroll
            for (int i = 0; i < 8; ++i) pa[i] = Ps[kk * PS_STRIDE + ty * 8 + i];
            float4 vb = *(const float4*)&Vs[kk * 64 + tx * 4];
#pragma unroll
            for (int i = 0; i < 8; ++i) {
                o[i][0] = fmaf(pa[i], vb.x, o[i][0]);
                o[i][1] = fmaf(pa[i], vb.y, o[i][1]);
                o[i][2] = fmaf(pa[i], vb.z, o[i][2]);
                o[i][3] = fmaf(pa[i], vb.w, o[i][3]);
            }
        }
    }

    const int b = bh >> 4;
    const int h = bh & 15;
#pragma unroll
    for (int i = 0; i < 8; ++i) {
        const int t = q0 + ty * 8 + i;
        const float inv = 1.0f / li[i];
        float4 ov;
        ov.x = o[i][0] * inv; ov.y = o[i][1] * inv;
        ov.z = o[i][2] * inv; ov.w = o[i][3] * inv;
        *(float4*)&g_att[((size_t)(b * SEQ) + t) * DIMC + h * HD + tx * 4] = ov;
    }
}

// ---------------------------------------------------------------------------
extern "C" void kernel_launch(void* const* d_in, const int* in_sizes, int n_in,
                              void* d_out, int out_size)
{
    const float* x      = (const float*)d_in[0];
    const float* W_qkv  = (const float*)d_in[1];
    const float* b_qkv  = (const float*)d_in[2];
    const float* W_proj = (const float*)d_in[3];
    const float* b_proj = (const float*)d_in[4];
    float* out = (float*)d_out;

    cudaFuncSetAttribute(gemm_mma_kernel<0>,
                         cudaFuncAttributeMaxDynamicSharedMemorySize, GEMM_SMEM_BYTES);
    cudaFuncSetAttribute(gemm_mma_kernel<1>,
                         cudaFuncAttributeMaxDynamicSharedMemorySize, GEMM_SMEM_BYTES);
    cudaFuncSetAttribute(attn_kernel,
                         cudaFuncAttributeMaxDynamicSharedMemorySize, ATTN_SMEM_BYTES);

    gemm_mma_kernel<0><<<dim3(24, 32), 256, GEMM_SMEM_BYTES>>>(x, W_qkv, b_qkv, nullptr);
    attn_kernel<<<dim3(16, 32), 256, ATTN_SMEM_BYTES>>>();
    gemm_mma_kernel<1><<<dim3(8, 32), 256, GEMM_SMEM_BYTES>>>(nullptr, W_proj, b_proj, out);
}